// round 6
// baseline (speedup 1.0000x reference)
#include <cuda_runtime.h>

#define BB 16
#define PP 16
#define CC 1024
#define DD 128

__device__ float g_partial[BB*32];   // 32 block-partials per batch
__device__ int   g_count[BB];        // arrivals (zero-init, self-reset)
__device__ int   g_done[BB];         // completions (zero-init, self-reset)

// ---------------------------------------------------------------------------
// Single kernel, single output pass:
//   grid 512 = (b,p) x 2 chunks; warp owns 64 candidates (2 per lane).
//   Phase 1: warp-dot scores (4 independent LDG.128 per iter), butterfly
//     broadcasts each score to all lanes; the OWNING lane exponentiates and
//     keeps it in a register. Masked candidates stay 0 (= exact reference).
//   Sync: block partial sum (fixed order) -> g_partial, arrive on g_count[b],
//     spin until all 32 batch blocks arrived (grid fully resident by
//     __launch_bounds__(256,4): 148*4=592 >= 512 blocks -> no deadlock).
//   Phase 2: every block sums the 32 partials in identical fixed order
//     (deterministic), scales its register exps, and writes the output ONCE
//     (coalesced). Last finisher resets counters for graph replay.
//   Row-constant score terms cancel in softmax; |score| <~ 1 so exp w/o max
//   subtraction is exact vs reference (validated rel_err ~1e-7 in R3-R5).
// ---------------------------------------------------------------------------
__global__ void __launch_bounds__(256, 4) k_fused(
    const float* __restrict__ cand_emb,
    const int*   __restrict__ cand_len,
    const float* __restrict__ score_w,
    float* __restrict__ out)
{
    __shared__ float sred[8];
    __shared__ float s_inv;

    int bp = blockIdx.x >> 1, chunk = blockIdx.x & 1;
    int b = bp >> 4;
    int t = threadIdx.x, wid = t >> 5, lane = t & 31;

    float4 w4 = ((const float4*)(score_w + 3*DD))[lane];
    int clen = cand_len[bp];
    const float4* __restrict__ ce =
        (const float4*)cand_emb + (size_t)bp * (CC*DD/4);

    int c0 = chunk*512 + wid*64;                 // warp's 64 candidates
    int nv = clen - c0; nv = nv < 0 ? 0 : (nv > 64 ? 64 : nv);

    float e_lo = 0.f, e_hi = 0.f;                // lane owns c0+lane, c0+32+lane

    int j = 0;
    for (; j + 4 <= nv; j += 4) {
        int c = c0 + j;
        float4 e0 = ce[(size_t)(c+0)*32 + lane];
        float4 e1 = ce[(size_t)(c+1)*32 + lane];
        float4 e2 = ce[(size_t)(c+2)*32 + lane];
        float4 e3 = ce[(size_t)(c+3)*32 + lane];
        float s0 = e0.x*w4.x + e0.y*w4.y + e0.z*w4.z + e0.w*w4.w;
        float s1 = e1.x*w4.x + e1.y*w4.y + e1.z*w4.z + e1.w*w4.w;
        float s2 = e2.x*w4.x + e2.y*w4.y + e2.z*w4.z + e2.w*w4.w;
        float s3 = e3.x*w4.x + e3.y*w4.y + e3.z*w4.z + e3.w*w4.w;
        #pragma unroll
        for (int o = 16; o > 0; o >>= 1) {       // full butterfly: all lanes get result
            s0 += __shfl_xor_sync(0xffffffffu, s0, o);
            s1 += __shfl_xor_sync(0xffffffffu, s1, o);
            s2 += __shfl_xor_sync(0xffffffffu, s2, o);
            s3 += __shfl_xor_sync(0xffffffffu, s3, o);
        }
        // owning lane selects its score and exponentiates (groups are 4-aligned,
        // so a group is entirely in the lo half (j<32) or hi half)
        int rel = (j < 32) ? (lane - j) : (lane - (j - 32));
        if (rel >= 0 && rel < 4) {
            float s = (rel == 0) ? s0 : (rel == 1) ? s1 : (rel == 2) ? s2 : s3;
            float x = __expf(s);
            if (j < 32) e_lo = x; else e_hi = x;
        }
    }
    for (; j < nv; j++) {                         // scalar tail
        int c = c0 + j;
        float4 e = ce[(size_t)c*32 + lane];
        float s = e.x*w4.x + e.y*w4.y + e.z*w4.z + e.w*w4.w;
        #pragma unroll
        for (int o = 16; o > 0; o >>= 1) s += __shfl_xor_sync(0xffffffffu, s, o);
        if (j < 32) { if (lane == j)      e_lo = __expf(s); }
        else        { if (lane == j - 32) e_hi = __expf(s); }
    }

    // ---- block partial (fixed order throughout) ----
    float mysum = e_lo + e_hi;
    #pragma unroll
    for (int o = 16; o > 0; o >>= 1)
        mysum += __shfl_xor_sync(0xffffffffu, mysum, o);
    if (lane == 0) sred[wid] = mysum;
    __syncthreads();
    if (t == 0) {
        float s = 0.f;
        #pragma unroll
        for (int w = 0; w < 8; w++) s += sred[w];
        int slot = ((bp & 15) << 1) | chunk;      // 0..31 within batch
        g_partial[b*32 + slot] = s;
        __threadfence();                          // release partial
        atomicAdd(&g_count[b], 1);
        // spin until all 32 batch blocks have published (grid fully resident)
        while (atomicAdd(&g_count[b], 0) < 32) { }
        __threadfence();                          // acquire partials
    }
    __syncthreads();

    // ---- every block: identical fixed-order total -> deterministic ----
    if (wid == 0) {
        float v = g_partial[b*32 + lane];
        #pragma unroll
        for (int o = 16; o > 0; o >>= 1)
            v += __shfl_xor_sync(0xffffffffu, v, o);
        if (lane == 0) s_inv = 1.0f / v;
    }
    __syncthreads();
    float inv = s_inv;

    // ---- single output store, coalesced 128B per half ----
    float* __restrict__ orow = out + (size_t)bp * CC + c0;
    orow[lane]      = e_lo * inv;
    orow[32 + lane] = e_hi * inv;

    // ---- reset counters for graph replay (last finisher; all reads done) ----
    __syncthreads();
    if (t == 0) {
        __threadfence();
        int old = atomicAdd(&g_done[b], 1);
        if (old == 31) { g_done[b] = 0; g_count[b] = 0; }
    }
}

// ---------------------------------------------------------------------------
extern "C" void kernel_launch(void* const* d_in, const int* in_sizes, int n_in,
                              void* d_out, int out_size)
{
    const float* cand_emb = (const float*)d_in[3];
    const int*   cand_len = (const int*)  d_in[4];
    const float* score_w  = (const float*)d_in[19];
    float* out = (float*)d_out;

    k_fused<<<BB*PP*2, 256>>>(cand_emb, cand_len, score_w, out);
}